// round 14
// baseline (speedup 1.0000x reference)
#include <cuda_runtime.h>
#include <cuda_fp16.h>
#include <math.h>

#define Bb 2
#define Tt 4096
#define DM 2048
#define NH 32
#define NKV 8
#define DH 64
#define SS 1028
#define SINKN 4
#define POS_SHIFT 3068

// ---------------- scratch (16B-aligned) --------------------------------------------
__device__ __align__(16) __half g_xh  [(size_t)Bb*Tt*DM];
__device__ __align__(16) __half g_wqh [(size_t)DM*DM];
__device__ __align__(16) __half g_wkvh[(size_t)1024*DM];
__device__ __align__(16) __half g_wph [(size_t)DM*DM];
__device__ __align__(16) __half g_ctxh[(size_t)Bb*Tt*DM];
__device__ __align__(16) __half g_Qh [(size_t)Bb*NH*Tt*DH];
__device__ __align__(16) __half g_Kh [(size_t)Bb*NKV*SS*DH];
__device__ __align__(16) __half g_vtm[(size_t)Bb*SS*512];
__device__ __align__(16) float2 g_rtab[(size_t)Tt*32];

// ---------------- helpers ------------------------------------------------------------
__device__ __forceinline__ void mma16h(float c[4], const unsigned a[4], const unsigned b[2]) {
    asm volatile("mma.sync.aligned.m16n8k16.row.col.f32.f16.f16.f32 "
        "{%0,%1,%2,%3},{%4,%5,%6,%7},{%8,%9},{%0,%1,%2,%3};"
        : "+f"(c[0]), "+f"(c[1]), "+f"(c[2]), "+f"(c[3])
        : "r"(a[0]), "r"(a[1]), "r"(a[2]), "r"(a[3]), "r"(b[0]), "r"(b[1]));
}
__device__ __forceinline__ void ldm_x4(unsigned &r0, unsigned &r1, unsigned &r2, unsigned &r3,
                                       unsigned addr) {
    asm volatile("ldmatrix.sync.aligned.m8n8.x4.shared.b16 {%0,%1,%2,%3}, [%4];"
        : "=r"(r0), "=r"(r1), "=r"(r2), "=r"(r3) : "r"(addr));
}
__device__ __forceinline__ void ldm_x4_t(unsigned &r0, unsigned &r1, unsigned &r2, unsigned &r3,
                                         unsigned addr) {
    asm volatile("ldmatrix.sync.aligned.m8n8.x4.trans.shared.b16 {%0,%1,%2,%3}, [%4];"
        : "=r"(r0), "=r"(r1), "=r"(r2), "=r"(r3) : "r"(addr));
}
__device__ __forceinline__ unsigned packh2(float lo, float hi) {
    __half2 h = __floats2half2_rn(lo, hi);
    return *reinterpret_cast<unsigned*>(&h);
}
__device__ __forceinline__ unsigned smem_u32(const void* p) {
    return (unsigned)__cvta_generic_to_shared(p);
}
__device__ __forceinline__ void cpa16(unsigned dst, const void* src) {
    asm volatile("cp.async.cg.shared.global [%0], [%1], 16;" :: "r"(dst), "l"(src));
}
__device__ __forceinline__ void cpa16z(unsigned dst, const void* src, unsigned sz) {
    asm volatile("cp.async.cg.shared.global [%0], [%1], 16, %2;" :: "r"(dst), "l"(src), "r"(sz));
}
__device__ __forceinline__ uint2 pack4(float4 v) {
    __half2 h0 = __floats2half2_rn(v.x, v.y);
    __half2 h1 = __floats2half2_rn(v.z, v.w);
    return make_uint2(*reinterpret_cast<unsigned*>(&h0), *reinterpret_cast<unsigned*>(&h1));
}

// ---------------- RoPE trig table ------------------------------------------------------
__global__ void k_rtab() {
    int idx = blockIdx.x * 256 + threadIdx.x;
    int i = idx & 31, t = idx >> 5;
    double inv = pow(10000.0, -(double)i / 32.0);
    double ang = (double)t * inv;
    g_rtab[idx] = make_float2((float)cos(ang), (float)sin(ang));
}

// ---------------- split kernels ----------------------------------------------------------
__global__ void k_split_x(const float4* __restrict__ s) {
    size_t i = (size_t)blockIdx.x * blockDim.x + threadIdx.x;
    *(uint2*)&g_xh[i * 4] = pack4(s[i]);
}
__global__ void k_split_w(const float4* __restrict__ wq, const float4* __restrict__ wk,
                          const float4* __restrict__ wv, const float4* __restrict__ wp) {
    size_t i = (size_t)blockIdx.x * 256 + threadIdx.x;
    const size_t NQ = (size_t)DM * DM / 4;
    const size_t NK = (size_t)512 * DM / 4;
    if (i < NQ) {
        *(uint2*)&g_wqh[i * 4] = pack4(wq[i]);
    } else if (i < NQ + NK) {
        size_t j = i - NQ;
        *(uint2*)&g_wkvh[j * 4] = pack4(wk[j]);
    } else if (i < NQ + 2 * NK) {
        size_t j = i - NQ - NK;
        *(uint2*)&g_wkvh[(size_t)512 * DM + j * 4] = pack4(wv[j]);
    } else {
        size_t j = i - NQ - 2 * NK;
        *(uint2*)&g_wph[j * 4] = pack4(wp[j]);
    }
}

// ---------------- fp16 GEMM core: 128 threads, 4 warps, warp tile 64x64, BK=32 -----------
#define SK3 40

template<int MODE>
__device__ __forceinline__ void gemm_core(int bxx, int byy, float* __restrict__ C,
                                          int M, int N, int K)
{
    const __half* A_ = (MODE == 2) ? g_ctxh : g_xh;
    const __half* W_ = (MODE == 0) ? g_wqh : (MODE == 1) ? g_wkvh : g_wph;

    __shared__ __align__(16) __half sm[2][2][128 * SK3];   // 40 KB
    int tid = threadIdx.x, lane = tid & 31, wid = tid >> 5;
    int wm = wid >> 1, wn = wid & 1, gp = lane >> 2, q = lane & 3;
    int bm = byy * 128, bn = bxx * 128;
    int lmr = lane & 15, lmk = (lane >> 4) * 8;

    float acc[4][8][4];
    #pragma unroll
    for (int mt = 0; mt < 4; mt++)
        #pragma unroll
        for (int nt = 0; nt < 8; nt++)
            #pragma unroll
            for (int i = 0; i < 4; i++) acc[mt][nt][i] = 0.f;

    // loader: 128 threads; thread handles rows row0 + j*32 (j=0..3), segment (tid&3)*8
    int row0 = tid >> 2, seg = (tid & 3) * 8;
    const __half* gaa[4];
    const __half* gbb[4];
    unsigned sa[2][4], sb[2][4];
    #pragma unroll
    for (int j = 0; j < 4; j++) {
        int r = row0 + j * 32;
        int arow = bm + r; if (arow > M - 1) arow = M - 1;
        int brow = bn + r; if (brow > N - 1) brow = N - 1;
        if (MODE == 1) {
            int ab = arow / SS, aj = arow % SS;
            int pos = (aj < SINKN) ? aj : aj + POS_SHIFT;
            gaa[j] = A_ + ((size_t)ab * Tt + pos) * DM + seg;
        } else {
            gaa[j] = A_ + (size_t)arow * K + seg;
        }
        gbb[j] = W_ + (size_t)brow * K + seg;
        #pragma unroll
        for (int s = 0; s < 2; s++) {
            sa[s][j] = smem_u32(&sm[s][0][r * SK3 + seg]);
            sb[s][j] = smem_u32(&sm[s][1][r * SK3 + seg]);
        }
    }

    int iters = K / 32;
    #pragma unroll
    for (int j = 0; j < 4; j++) { cpa16(sa[0][j], gaa[j]); cpa16(sb[0][j], gbb[j]); }
    asm volatile("cp.async.commit_group;");

    for (int i = 0; i < iters; i++) {
        asm volatile("cp.async.wait_group 0;");
        __syncthreads();
        if (i + 1 < iters) {
            int st = (i + 1) & 1, k0 = (i + 1) * 32;
            #pragma unroll
            for (int j = 0; j < 4; j++) {
                cpa16(sa[st][j], gaa[j] + k0);
                cpa16(sb[st][j], gbb[j] + k0);
            }
            asm volatile("cp.async.commit_group;");
        }

        int cur = i & 1;
        unsigned abase = smem_u32(&sm[cur][0][0]);
        unsigned bbase = smem_u32(&sm[cur][1][0]);

        unsigned a[4][2][4];   // [mt][kk]
        #pragma unroll
        for (int mt = 0; mt < 4; mt++)
            #pragma unroll
            for (int kk = 0; kk < 2; kk++)
                ldm_x4(a[mt][kk][0], a[mt][kk][1], a[mt][kk][2], a[mt][kk][3],
                       abase + ((wm*64 + mt*16 + lmr) * SK3 + kk*16 + lmk) * 2);

        #pragma unroll
        for (int p = 0; p < 4; p++) {
            #pragma unroll
            for (int kk = 0; kk < 2; kk++) {
                unsigned r0, r1, r2, r3;
                ldm_x4(r0, r1, r2, r3,
                       bbase + ((wn*64 + p*16 + lmr) * SK3 + kk*16 + lmk) * 2);
                unsigned b0[2] = { r0, r2 }, b1[2] = { r1, r3 };
                #pragma unroll
                for (int mt = 0; mt < 4; mt++) {
                    mma16h(acc[mt][2*p],   a[mt][kk], b0);
                    mma16h(acc[mt][2*p+1], a[mt][kk], b1);
                }
            }
        }
    }

    // ---------------- epilogues ----------------
    int cb = bn + wn * 64;
    if (MODE == 0) {
        int h = cb >> 6;
        #pragma unroll
        for (int mt = 0; mt < 4; mt++) {
            int r = bm + wm * 64 + mt * 16 + gp;
            #pragma unroll
            for (int half_ = 0; half_ < 2; half_++) {
                int rr = r + half_ * 8;
                int b = rr >> 12, t = rr & 4095;
                size_t o = (((size_t)b * NH + h) * Tt + t) * DH;
                #pragma unroll
                for (int nt = 0; nt < 4; nt++) {
                    int i2 = nt * 8 + q * 2;
                    float x1a = acc[mt][nt][2*half_],     x1b = acc[mt][nt][2*half_ + 1];
                    float x2a = acc[mt][nt + 4][2*half_], x2b = acc[mt][nt + 4][2*half_ + 1];
                    float2 ca  = g_rtab[t * 32 + i2];
                    float2 cbv = g_rtab[t * 32 + i2 + 1];
                    *(unsigned*)&g_Qh[o + i2] =
                        packh2(0.125f * (x1a * ca.x - x2a * ca.y),
                               0.125f * (x1b * cbv.x - x2b * cbv.y));
                    *(unsigned*)&g_Qh[o + i2 + 32] =
                        packh2(0.125f * (x2a * ca.x + x1a * ca.y),
                               0.125f * (x2b * cbv.x + x1b * cbv.y));
                }
            }
        }
    } else if (MODE == 1) {
        int hb = cb >> 6;
        #pragma unroll
        for (int mt = 0; mt < 4; mt++) {
            int r = bm + wm * 64 + mt * 16 + gp;
            #pragma unroll
            for (int half_ = 0; half_ < 2; half_++) {
                int rr = r + half_ * 8;
                if (rr >= M) continue;
                int b = (rr >= SS) ? 1 : 0;
                int j = rr - b * SS;
                if (hb < 8) {
                    int pos = (j < SINKN) ? j : j + POS_SHIFT;
                    size_t o = (((size_t)b * NKV + hb) * SS + j) * DH;
                    #pragma unroll
                    for (int nt = 0; nt < 4; nt++) {
                        int i2 = nt * 8 + q * 2;
                        float x1a = acc[mt][nt][2*half_],     x1b = acc[mt][nt][2*half_ + 1];
                        float x2a = acc[mt][nt + 4][2*half_], x2b = acc[mt][nt + 4][2*half_ + 1];
                        float2 ca  = g_rtab[pos * 32 + i2];
                        float2 cbv = g_rtab[pos * 32 + i2 + 1];
                        *(unsigned*)&g_Kh[o + i2] =
                            packh2(x1a * ca.x - x2a * ca.y, x1b * cbv.x - x2b * cbv.y);
                        *(unsigned*)&g_Kh[o + i2 + 32] =
                            packh2(x2a * ca.x + x1a * ca.y, x2b * cbv.x + x1b * cbv.y);
                    }
                } else {
                    size_t o = ((size_t)b * SS + j) * 512 + (hb - 8) * 64;
                    #pragma unroll
                    for (int nt = 0; nt < 8; nt++) {
                        int d = nt * 8 + q * 2;
                        *(unsigned*)&g_vtm[o + d] =
                            packh2(acc[mt][nt][2*half_], acc[mt][nt][2*half_ + 1]);
                    }
                }
            }
        }
    } else {
        #pragma unroll
        for (int mt = 0; mt < 4; mt++) {
            int r = bm + wm * 64 + mt * 16 + gp;
            #pragma unroll
            for (int nt = 0; nt < 8; nt++) {
                int cc = cb + nt * 8 + q * 2;
                C[(size_t)r * N + cc]       = acc[mt][nt][0];
                C[(size_t)r * N + cc + 1]   = acc[mt][nt][1];
                C[(size_t)(r+8) * N + cc]   = acc[mt][nt][2];
                C[(size_t)(r+8) * N + cc+1] = acc[mt][nt][3];
            }
        }
    }
}

// merged Q + KV projection (1160 blocks: 1024 Q tiles + 136 KV tiles)
__global__ void __launch_bounds__(128, 2) k_gemm_qkv() {
    int bid = blockIdx.x;
    if (bid < 1024) {
        gemm_core<0>(bid & 15, bid >> 4, nullptr, Bb * Tt, DM, DM);
    } else {
        int r = bid - 1024;
        gemm_core<1>(r & 7, r >> 3, nullptr, Bb * SS, 1024, DM);
    }
}
__global__ void __launch_bounds__(128, 2) k_proj(float* __restrict__ out) {
    gemm_core<2>(blockIdx.x, blockIdx.y, out, Bb * Tt, DM, DM);
}

// ---------------- fused flash attention (unchanged from round 13) -------------------------
__global__ void __launch_bounds__(256, 2) k_flash() {
    __shared__ __align__(16) __half Ks[2][64 * 72];
    __shared__ __align__(16) __half Vs[2][64 * 72];
    int tid = threadIdx.x, lane = tid & 31, wid = tid >> 5;
    int gp = lane >> 2, q = lane & 3;
    int lmr = lane & 15, lmk = (lane >> 4) * 8;
    int t0 = blockIdx.x * 128;
    int z = blockIdx.y;
    int b = z >> 5, h = z & 31, kvh = h >> 2;
    int bk = b * NKV + kvh;
    const __half* Qp = g_Qh + (size_t)z * Tt * DH;
    const __half* Kp = g_Kh + (size_t)bk * SS * DH;
    const __half* Vp = g_vtm + (size_t)b * SS * 512 + kvh * 64;

    int t_r0 = t0 + wid * 16 + gp;
    int t_r1 = t_r0 + 8;
    int warp_tmin = t0 + wid * 16;
    int s_end = min(SS, t0 + 128);
    int ntiles = (s_end + 63) >> 6;

    unsigned kbs[2] = { smem_u32(Ks[0]), smem_u32(Ks[1]) };
    unsigned vbs[2] = { smem_u32(Vs[0]), smem_u32(Vs[1]) };

    auto load_tile = [&](int s0, int st) {
        #pragma unroll
        for (int c = 0; c < 2; c++) {
            int f = c * 256 + tid;
            int r = f >> 3, sg = (f & 7) * 8;
            int srow = s0 + r;
            unsigned sz = (srow < SS) ? 16u : 0u;
            cpa16z(kbs[st] + (r * 72 + sg) * 2, Kp + (size_t)srow * DH + sg, sz);
            cpa16z(vbs[st] + (r * 72 + sg) * 2, Vp + (size_t)srow * 512 + sg, sz);
        }
        asm volatile("cp.async.commit_group;");
    };

    unsigned qa[4][4];
    {
        const unsigned* uQ0 = (const unsigned*)(Qp + (size_t)t_r0 * DH);
        const unsigned* uQ1 = (const unsigned*)(Qp + (size_t)t_r1 * DH);
        #pragma unroll
        for (int kk = 0; kk < 4; kk++) {
            qa[kk][0] = uQ0[kk * 8 + q];
            qa[kk][1] = uQ1[kk * 8 + q];
            qa[kk][2] = uQ0[kk * 8 + q + 4];
            qa[kk][3] = uQ1[kk * 8 + q + 4];
        }
    }

    float oacc[8][4];
    #pragma unroll
    for (int nt = 0; nt < 8; nt++)
        #pragma unroll
        for (int i = 0; i < 4; i++) oacc[nt][i] = 0.f;
    float m0 = -1e30f, m1 = -1e30f, l0 = 0.f, l1 = 0.f;

    load_tile(0, 0);

    for (int ti = 0; ti < ntiles; ti++) {
        int s0 = ti * 64;
        asm volatile("cp.async.wait_group 0;");
        __syncthreads();
        if (ti + 1 < ntiles) load_tile((ti + 1) * 64, (ti + 1) & 1);

        int st = ti & 1;
        unsigned kb = kbs[st], vb = vbs[st];

        float sacc[8][4];
        #pragma unroll
        for (int nt = 0; nt < 8; nt++)
            #pragma unroll
            for (int i = 0; i < 4; i++) sacc[nt][i] = 0.f;
        #pragma unroll
        for (int kk = 0; kk < 4; kk++) {
            #pragma unroll
            for (int p = 0; p < 4; p++) {
                unsigned r0, r1, r2, r3;
                ldm_x4(r0, r1, r2, r3, kb + ((p*16 + lmr) * 72 + kk*16 + lmk) * 2);
                unsigned b0[2] = { r0, r2 }, b1[2] = { r1, r3 };
                mma16h(sacc[2*p],   qa[kk], b0);
                mma16h(sacc[2*p+1], qa[kk], b1);
            }
        }

        bool nomask = (s0 + 63 <= warp_tmin) && (s0 + 64 <= SS);
        if (!nomask) {
            #pragma unroll
            for (int nt = 0; nt < 8; nt++) {
                int j = s0 + nt*8 + q*2;
                if (!(j     <= t_r0 && j     < SS)) sacc[nt][0] = -1e30f;
                if (!(j + 1 <= t_r0 && j + 1 < SS)) sacc[nt][1] = -1e30f;
                if (!(j     <= t_r1 && j     < SS)) sacc[nt][2] = -1e30f;
                if (!(j + 1 <= t_r1 && j + 1 < SS)) sacc[nt][3] = -1e30f;
            }
        }

        float mx0 = -1e30f, mx1 = -1e30f;
        #pragma unroll
        for (int nt = 0; nt < 8; nt++) {
            mx0 = fmaxf(mx0, fmaxf(sacc[nt][0], sacc[nt][1]));
            mx1 = fmaxf(mx1, fmaxf(sacc[nt][2], sacc[nt][3]));
        }
        mx0 = fmaxf(mx0, __shfl_xor_sync(0xffffffffu, mx0, 1));
        mx0 = fmaxf(mx0, __shfl_xor_sync(0xffffffffu, mx0, 2));
        mx1 = fmaxf(mx1, __shfl_xor_sync(0xffffffffu, mx1, 1));
        mx1 = fmaxf(mx1, __shfl_xor_sync(0xffffffffu, mx1, 2));
        float mn0 = fmaxf(m0, mx0), mn1 = fmaxf(m1, mx1);
        float al0 = __expf(m0 - mn0), al1 = __expf(m1 - mn1);
        float rs0 = 0.f, rs1 = 0.f;
        #pragma unroll
        for (int nt = 0; nt < 8; nt++) {
            float p0 = __expf(sacc[nt][0] - mn0); sacc[nt][0] = p0; rs0 += p0;
            float p1 = __expf(sacc[nt][1] - mn0); sacc[nt][1] = p1; rs0 += p1;
            float p2 = __expf(sacc[nt][2] - mn1); sacc[nt][2] = p2; rs1 += p2;
            float p3 = __expf(sacc[nt][3] - mn1); sacc[nt][3] = p3; rs1 += p3;
        }
        rs0 += __shfl_xor_sync(0xffffffffu, rs0, 1);
        rs0 += __shfl_xor_sync(0xffffffffu, rs0, 2);
        rs1 += __shfl_xor_sync(0xffffffffu, rs1, 1);
        rs1 += __shfl_xor_sync(0xffffffffu, rs1, 2);
        l0 = l0 * al0 + rs0;
        l1 = l1 * al1 + rs1;
        m0 = mn0; m1 = mn1;
        #pragma unroll
        for (int nt = 0; nt < 8; nt++) {
            oacc[nt][0] *= al0; oacc[nt][1] *= al0;
            oacc[nt][2] *= al1; oacc[nt][3] *= al1;
        }

        #pragma unroll
        for (int kt = 0; kt < 4; kt++) {
            unsigned pa[4];
            pa[0] = packh2(sacc[2*kt][0],     sacc[2*kt][1]);
            pa[1] = packh2(sacc[2*kt][2],     sacc[2*kt][3]);
            pa[2] = packh2(sacc[2*kt + 1][0], sacc[2*kt + 1][1]);
            pa[3] = packh2(sacc[2*kt + 1][2], sacc[2*kt + 1][3]);
            #pragma unroll
            for (int p = 0; p < 4; p++) {
                unsigned r0, r1, r2, r3;
                ldm_x4_t(r0, r1, r2, r3, vb + ((kt*16 + lmr) * 72 + p*16 + lmk) * 2);
                unsigned b0[2] = { r0, r1 }, b1[2] = { r2, r3 };
                mma16h(oacc[2*p],   pa, b0);
                mma16h(oacc[2*p+1], pa, b1);
            }
        }
    }

    float inv0 = 1.f / l0, inv1 = 1.f / l1;
    size_t r0 = ((size_t)b * Tt + t_r0) * DM + h * DH;
    size_t r1 = ((size_t)b * Tt + t_r1) * DM + h * DH;
    #pragma unroll
    for (int nt = 0; nt < 8; nt++) {
        int d = nt*8 + q*2;
        g_ctxh[r0 + d]     = __float2half_rn(oacc[nt][0] * inv0);
        g_ctxh[r0 + d + 1] = __float2half_rn(oacc[nt][1] * inv0);
        g_ctxh[r1 + d]     = __float2half_rn(oacc[nt][2] * inv1);
        g_ctxh[r1 + d + 1] = __float2half_rn(oacc[nt][3] * inv1);
    }
}

// ---------------- launch -------------------------------------------------------------------
extern "C" void kernel_launch(void* const* d_in, const int* in_sizes, int n_in,
                              void* d_out, int out_size) {
    const float* x  = (const float*)d_in[0];
    const float* wq = (const float*)d_in[1];
    const float* wk = (const float*)d_in[2];
    const float* wv = (const float*)d_in[3];
    const float* wp = (const float*)d_in[4];
    float* out = (float*)d_out;

    k_rtab   <<<(Tt * 32) / 256, 256>>>();
    k_split_x<<<(size_t)(Bb*Tt*DM) / 1024, 256>>>((const float4*)x);
    k_split_w<<<10240, 256>>>((const float4*)wq, (const float4*)wk,
                              (const float4*)wv, (const float4*)wp);

    k_gemm_qkv<<<1024 + 136, 128>>>();

    k_flash<<<dim3(Tt / 128, Bb * NH), 256>>>();

    k_proj<<<dim3(DM / 128, (Bb * Tt) / 128), 128>>>(out);
}

// round 15
// speedup vs baseline: 1.0157x; 1.0157x over previous
#include <cuda_runtime.h>
#include <cuda_fp16.h>
#include <math.h>

#define Bb 2
#define Tt 4096
#define DM 2048
#define NH 32
#define NKV 8
#define DH 64
#define SS 1028
#define SINKN 4
#define POS_SHIFT 3068

// ---------------- scratch (16B-aligned) --------------------------------------------
__device__ __align__(16) __half g_xh  [(size_t)Bb*Tt*DM];
__device__ __align__(16) __half g_wqh [(size_t)DM*DM];
__device__ __align__(16) __half g_wkvh[(size_t)1024*DM];
__device__ __align__(16) __half g_wph [(size_t)DM*DM];
__device__ __align__(16) __half g_ctxh[(size_t)Bb*Tt*DM];
__device__ __align__(16) __half g_Qh [(size_t)Bb*NH*Tt*DH];
__device__ __align__(16) __half g_Kh [(size_t)Bb*NKV*SS*DH];
__device__ __align__(16) __half g_vtm[(size_t)Bb*SS*512];
__device__ __align__(16) float2 g_rtab[(size_t)Tt*32];

// ---------------- helpers ------------------------------------------------------------
__device__ __forceinline__ void mma16h(float c[4], const unsigned a[4], const unsigned b[2]) {
    asm volatile("mma.sync.aligned.m16n8k16.row.col.f32.f16.f16.f32 "
        "{%0,%1,%2,%3},{%4,%5,%6,%7},{%8,%9},{%0,%1,%2,%3};"
        : "+f"(c[0]), "+f"(c[1]), "+f"(c[2]), "+f"(c[3])
        : "r"(a[0]), "r"(a[1]), "r"(a[2]), "r"(a[3]), "r"(b[0]), "r"(b[1]));
}
__device__ __forceinline__ void ldm_x4(unsigned &r0, unsigned &r1, unsigned &r2, unsigned &r3,
                                       unsigned addr) {
    asm volatile("ldmatrix.sync.aligned.m8n8.x4.shared.b16 {%0,%1,%2,%3}, [%4];"
        : "=r"(r0), "=r"(r1), "=r"(r2), "=r"(r3) : "r"(addr));
}
__device__ __forceinline__ void ldm_x4_t(unsigned &r0, unsigned &r1, unsigned &r2, unsigned &r3,
                                         unsigned addr) {
    asm volatile("ldmatrix.sync.aligned.m8n8.x4.trans.shared.b16 {%0,%1,%2,%3}, [%4];"
        : "=r"(r0), "=r"(r1), "=r"(r2), "=r"(r3) : "r"(addr));
}
__device__ __forceinline__ unsigned packh2(float lo, float hi) {
    __half2 h = __floats2half2_rn(lo, hi);
    return *reinterpret_cast<unsigned*>(&h);
}
__device__ __forceinline__ unsigned smem_u32(const void* p) {
    return (unsigned)__cvta_generic_to_shared(p);
}
__device__ __forceinline__ void cpa16(unsigned dst, const void* src) {
    asm volatile("cp.async.cg.shared.global [%0], [%1], 16;" :: "r"(dst), "l"(src));
}
__device__ __forceinline__ void cpa16z(unsigned dst, const void* src, unsigned sz) {
    asm volatile("cp.async.cg.shared.global [%0], [%1], 16, %2;" :: "r"(dst), "l"(src), "r"(sz));
}
__device__ __forceinline__ uint2 pack4(float4 v) {
    __half2 h0 = __floats2half2_rn(v.x, v.y);
    __half2 h1 = __floats2half2_rn(v.z, v.w);
    return make_uint2(*reinterpret_cast<unsigned*>(&h0), *reinterpret_cast<unsigned*>(&h1));
}

// ---------------- RoPE trig table ------------------------------------------------------
__global__ void k_rtab() {
    int idx = blockIdx.x * 256 + threadIdx.x;
    int i = idx & 31, t = idx >> 5;
    double inv = pow(10000.0, -(double)i / 32.0);
    double ang = (double)t * inv;
    g_rtab[idx] = make_float2((float)cos(ang), (float)sin(ang));
}

// ---------------- split kernels ----------------------------------------------------------
__global__ void k_split_x(const float4* __restrict__ s) {
    size_t i = (size_t)blockIdx.x * blockDim.x + threadIdx.x;
    *(uint2*)&g_xh[i * 4] = pack4(s[i]);
}
__global__ void k_split_w(const float4* __restrict__ wq, const float4* __restrict__ wk,
                          const float4* __restrict__ wv, const float4* __restrict__ wp) {
    size_t i = (size_t)blockIdx.x * 256 + threadIdx.x;
    const size_t NQ = (size_t)DM * DM / 4;
    const size_t NK = (size_t)512 * DM / 4;
    if (i < NQ) {
        *(uint2*)&g_wqh[i * 4] = pack4(wq[i]);
    } else if (i < NQ + NK) {
        size_t j = i - NQ;
        *(uint2*)&g_wkvh[j * 4] = pack4(wk[j]);
    } else if (i < NQ + 2 * NK) {
        size_t j = i - NQ - NK;
        *(uint2*)&g_wkvh[(size_t)512 * DM + j * 4] = pack4(wv[j]);
    } else {
        size_t j = i - NQ - 2 * NK;
        *(uint2*)&g_wph[j * 4] = pack4(wp[j]);
    }
}

// ---------------- fp16 GEMM core: 256 thr, warp tile 32x64, BK=32, 3-stage ---------------
#define SK3 40
#define STAGE_H (2 * 128 * SK3)          // halfs per stage (A+B planes)
#define GSMEM_B (3 * STAGE_H * 2)        // 61440 bytes

template<int MODE>
__device__ __forceinline__ void gemm_core(int bxx, int byy, float* __restrict__ C,
                                          int M, int N, int K)
{
    const __half* A_ = (MODE == 2) ? g_ctxh : g_xh;
    const __half* W_ = (MODE == 0) ? g_wqh : (MODE == 1) ? g_wkvh : g_wph;

    extern __shared__ __align__(16) __half dsm[];
    int tid = threadIdx.x, lane = tid & 31, wid = tid >> 5;
    int wm = wid >> 1, wn = wid & 1, gp = lane >> 2, q = lane & 3;
    int bm = byy * 128, bn = bxx * 128;
    int lmr = lane & 15, lmk = (lane >> 4) * 8;

    float acc[2][8][4];
    #pragma unroll
    for (int mt = 0; mt < 2; mt++)
        #pragma unroll
        for (int nt = 0; nt < 8; nt++)
            #pragma unroll
            for (int i = 0; i < 4; i++) acc[mt][nt][i] = 0.f;

    // loader: thread handles rows row0 + j*64 (j=0,1), segment (tid&3)*8 halfs
    int row0 = tid >> 2, seg = (tid & 3) * 8;
    const __half* gaa[2];
    const __half* gbb[2];
    unsigned sa[3][2], sb[3][2];
    #pragma unroll
    for (int j = 0; j < 2; j++) {
        int r = row0 + j * 64;
        int arow = bm + r; if (arow > M - 1) arow = M - 1;
        int brow = bn + r; if (brow > N - 1) brow = N - 1;
        if (MODE == 1) {
            int ab = arow / SS, aj = arow % SS;
            int pos = (aj < SINKN) ? aj : aj + POS_SHIFT;
            gaa[j] = A_ + ((size_t)ab * Tt + pos) * DM + seg;
        } else {
            gaa[j] = A_ + (size_t)arow * K + seg;
        }
        gbb[j] = W_ + (size_t)brow * K + seg;
        #pragma unroll
        for (int s = 0; s < 3; s++) {
            sa[s][j] = smem_u32(&dsm[s * STAGE_H + r * SK3 + seg]);
            sb[s][j] = smem_u32(&dsm[s * STAGE_H + 128 * SK3 + r * SK3 + seg]);
        }
    }

    int iters = K / 32;
    // prologue: stages 0 and 1
    #pragma unroll
    for (int j = 0; j < 2; j++) { cpa16(sa[0][j], gaa[j]); cpa16(sb[0][j], gbb[j]); }
    asm volatile("cp.async.commit_group;");
    #pragma unroll
    for (int j = 0; j < 2; j++) { cpa16(sa[1][j], gaa[j] + 32); cpa16(sb[1][j], gbb[j] + 32); }
    asm volatile("cp.async.commit_group;");

    for (int i = 0; i < iters; i++) {
        if (i == iters - 1) asm volatile("cp.async.wait_group 0;");
        else                asm volatile("cp.async.wait_group 1;");
        __syncthreads();
        if (i + 2 < iters) {
            int st = (i + 2) % 3, k0 = (i + 2) * 32;
            #pragma unroll
            for (int j = 0; j < 2; j++) {
                cpa16(sa[st][j], gaa[j] + k0);
                cpa16(sb[st][j], gbb[j] + k0);
            }
            asm volatile("cp.async.commit_group;");
        }

        int cur = i % 3;
        unsigned abase = smem_u32(&dsm[cur * STAGE_H]);
        unsigned bbase = abase + 128 * SK3 * 2;

        unsigned a[2][2][4];   // [mt][kk]
        #pragma unroll
        for (int mt = 0; mt < 2; mt++)
            #pragma unroll
            for (int kk = 0; kk < 2; kk++)
                ldm_x4(a[mt][kk][0], a[mt][kk][1], a[mt][kk][2], a[mt][kk][3],
                       abase + ((wm*32 + mt*16 + lmr) * SK3 + kk*16 + lmk) * 2);

        #pragma unroll
        for (int p = 0; p < 4; p++) {
            #pragma unroll
            for (int kk = 0; kk < 2; kk++) {
                unsigned r0, r1, r2, r3;
                ldm_x4(r0, r1, r2, r3,
                       bbase + ((wn*64 + p*16 + lmr) * SK3 + kk*16 + lmk) * 2);
                unsigned b0[2] = { r0, r2 }, b1[2] = { r1, r3 };
                mma16h(acc[0][2*p],   a[0][kk], b0);
                mma16h(acc[1][2*p],   a[1][kk], b0);
                mma16h(acc[0][2*p+1], a[0][kk], b1);
                mma16h(acc[1][2*p+1], a[1][kk], b1);
            }
        }
    }

    // ---------------- epilogues (identical to round 13) ----------------
    int cb = bn + wn * 64;
    if (MODE == 0) {
        int h = cb >> 6;
        #pragma unroll
        for (int mt = 0; mt < 2; mt++) {
            int r = bm + wm * 32 + mt * 16 + gp;
            #pragma unroll
            for (int half_ = 0; half_ < 2; half_++) {
                int rr = r + half_ * 8;
                int b = rr >> 12, t = rr & 4095;
                size_t o = (((size_t)b * NH + h) * Tt + t) * DH;
                #pragma unroll
                for (int nt = 0; nt < 4; nt++) {
                    int i2 = nt * 8 + q * 2;
                    float x1a = acc[mt][nt][2*half_],     x1b = acc[mt][nt][2*half_ + 1];
                    float x2a = acc[mt][nt + 4][2*half_], x2b = acc[mt][nt + 4][2*half_ + 1];
                    float2 ca  = g_rtab[t * 32 + i2];
                    float2 cbv = g_rtab[t * 32 + i2 + 1];
                    *(unsigned*)&g_Qh[o + i2] =
                        packh2(0.125f * (x1a * ca.x - x2a * ca.y),
                               0.125f * (x1b * cbv.x - x2b * cbv.y));
                    *(unsigned*)&g_Qh[o + i2 + 32] =
                        packh2(0.125f * (x2a * ca.x + x1a * ca.y),
                               0.125f * (x2b * cbv.x + x1b * cbv.y));
                }
            }
        }
    } else if (MODE == 1) {
        int hb = cb >> 6;
        #pragma unroll
        for (int mt = 0; mt < 2; mt++) {
            int r = bm + wm * 32 + mt * 16 + gp;
            #pragma unroll
            for (int half_ = 0; half_ < 2; half_++) {
                int rr = r + half_ * 8;
                if (rr >= M) continue;
                int b = (rr >= SS) ? 1 : 0;
                int j = rr - b * SS;
                if (hb < 8) {
                    int pos = (j < SINKN) ? j : j + POS_SHIFT;
                    size_t o = (((size_t)b * NKV + hb) * SS + j) * DH;
                    #pragma unroll
                    for (int nt = 0; nt < 4; nt++) {
                        int i2 = nt * 8 + q * 2;
                        float x1a = acc[mt][nt][2*half_],     x1b = acc[mt][nt][2*half_ + 1];
                        float x2a = acc[mt][nt + 4][2*half_], x2b = acc[mt][nt + 4][2*half_ + 1];
                        float2 ca  = g_rtab[pos * 32 + i2];
                        float2 cbv = g_rtab[pos * 32 + i2 + 1];
                        *(unsigned*)&g_Kh[o + i2] =
                            packh2(x1a * ca.x - x2a * ca.y, x1b * cbv.x - x2b * cbv.y);
                        *(unsigned*)&g_Kh[o + i2 + 32] =
                            packh2(x2a * ca.x + x1a * ca.y, x2b * cbv.x + x1b * cbv.y);
                    }
                } else {
                    size_t o = ((size_t)b * SS + j) * 512 + (hb - 8) * 64;
                    #pragma unroll
                    for (int nt = 0; nt < 8; nt++) {
                        int d = nt * 8 + q * 2;
                        *(unsigned*)&g_vtm[o + d] =
                            packh2(acc[mt][nt][2*half_], acc[mt][nt][2*half_ + 1]);
                    }
                }
            }
        }
    } else {
        #pragma unroll
        for (int mt = 0; mt < 2; mt++) {
            int r = bm + wm * 32 + mt * 16 + gp;
            #pragma unroll
            for (int nt = 0; nt < 8; nt++) {
                int cc = cb + nt * 8 + q * 2;
                C[(size_t)r * N + cc]       = acc[mt][nt][0];
                C[(size_t)r * N + cc + 1]   = acc[mt][nt][1];
                C[(size_t)(r+8) * N + cc]   = acc[mt][nt][2];
                C[(size_t)(r+8) * N + cc+1] = acc[mt][nt][3];
            }
        }
    }
}

// merged Q + KV projection (1160 blocks: 1024 Q tiles + 136 KV tiles)
__global__ void __launch_bounds__(256, 2) k_gemm_qkv() {
    int bid = blockIdx.x;
    if (bid < 1024) {
        gemm_core<0>(bid & 15, bid >> 4, nullptr, Bb * Tt, DM, DM);
    } else {
        int r = bid - 1024;
        gemm_core<1>(r & 7, r >> 3, nullptr, Bb * SS, 1024, DM);
    }
}
__global__ void __launch_bounds__(256, 2) k_proj(float* __restrict__ out) {
    gemm_core<2>(blockIdx.x, blockIdx.y, out, Bb * Tt, DM, DM);
}

// ---------------- fused flash attention (identical to round 13) ---------------------------
__global__ void __launch_bounds__(256, 2) k_flash() {
    __shared__ __align__(16) __half Ks[2][64 * 72];
    __shared__ __align__(16) __half Vs[2][64 * 72];
    int tid = threadIdx.x, lane = tid & 31, wid = tid >> 5;
    int gp = lane >> 2, q = lane & 3;
    int lmr = lane & 15, lmk = (lane >> 4) * 8;
    int t0 = blockIdx.x * 128;
    int z = blockIdx.y;
    int b = z >> 5, h = z & 31, kvh = h >> 2;
    int bk = b * NKV + kvh;
    const __half* Qp = g_Qh + (size_t)z * Tt * DH;
    const __half* Kp = g_Kh + (size_t)bk * SS * DH;
    const __half* Vp = g_vtm + (size_t)b * SS * 512 + kvh * 64;

    int t_r0 = t0 + wid * 16 + gp;
    int t_r1 = t_r0 + 8;
    int warp_tmin = t0 + wid * 16;
    int s_end = min(SS, t0 + 128);
    int ntiles = (s_end + 63) >> 6;

    unsigned kbs[2] = { smem_u32(Ks[0]), smem_u32(Ks[1]) };
    unsigned vbs[2] = { smem_u32(Vs[0]), smem_u32(Vs[1]) };

    auto load_tile = [&](int s0, int st) {
        #pragma unroll
        for (int c = 0; c < 2; c++) {
            int f = c * 256 + tid;
            int r = f >> 3, sg = (f & 7) * 8;
            int srow = s0 + r;
            unsigned sz = (srow < SS) ? 16u : 0u;
            cpa16z(kbs[st] + (r * 72 + sg) * 2, Kp + (size_t)srow * DH + sg, sz);
            cpa16z(vbs[st] + (r * 72 + sg) * 2, Vp + (size_t)srow * 512 + sg, sz);
        }
        asm volatile("cp.async.commit_group;");
    };

    unsigned qa[4][4];
    {
        const unsigned* uQ0 = (const unsigned*)(Qp + (size_t)t_r0 * DH);
        const unsigned* uQ1 = (const unsigned*)(Qp + (size_t)t_r1 * DH);
        #pragma unroll
        for (int kk = 0; kk < 4; kk++) {
            qa[kk][0] = uQ0[kk * 8 + q];
            qa[kk][1] = uQ1[kk * 8 + q];
            qa[kk][2] = uQ0[kk * 8 + q + 4];
            qa[kk][3] = uQ1[kk * 8 + q + 4];
        }
    }

    float oacc[8][4];
    #pragma unroll
    for (int nt = 0; nt < 8; nt++)
        #pragma unroll
        for (int i = 0; i < 4; i++) oacc[nt][i] = 0.f;
    float m0 = -1e30f, m1 = -1e30f, l0 = 0.f, l1 = 0.f;

    load_tile(0, 0);

    for (int ti = 0; ti < ntiles; ti++) {
        int s0 = ti * 64;
        asm volatile("cp.async.wait_group 0;");
        __syncthreads();
        if (ti + 1 < ntiles) load_tile((ti + 1) * 64, (ti + 1) & 1);

        int st = ti & 1;
        unsigned kb = kbs[st], vb = vbs[st];

        float sacc[8][4];
        #pragma unroll
        for (int nt = 0; nt < 8; nt++)
            #pragma unroll
            for (int i = 0; i < 4; i++) sacc[nt][i] = 0.f;
        #pragma unroll
        for (int kk = 0; kk < 4; kk++) {
            #pragma unroll
            for (int p = 0; p < 4; p++) {
                unsigned r0, r1, r2, r3;
                ldm_x4(r0, r1, r2, r3, kb + ((p*16 + lmr) * 72 + kk*16 + lmk) * 2);
                unsigned b0[2] = { r0, r2 }, b1[2] = { r1, r3 };
                mma16h(sacc[2*p],   qa[kk], b0);
                mma16h(sacc[2*p+1], qa[kk], b1);
            }
        }

        bool nomask = (s0 + 63 <= warp_tmin) && (s0 + 64 <= SS);
        if (!nomask) {
            #pragma unroll
            for (int nt = 0; nt < 8; nt++) {
                int j = s0 + nt*8 + q*2;
                if (!(j     <= t_r0 && j     < SS)) sacc[nt][0] = -1e30f;
                if (!(j + 1 <= t_r0 && j + 1 < SS)) sacc[nt][1] = -1e30f;
                if (!(j     <= t_r1 && j     < SS)) sacc[nt][2] = -1e30f;
                if (!(j + 1 <= t_r1 && j + 1 < SS)) sacc[nt][3] = -1e30f;
            }
        }

        float mx0 = -1e30f, mx1 = -1e30f;
        #pragma unroll
        for (int nt = 0; nt < 8; nt++) {
            mx0 = fmaxf(mx0, fmaxf(sacc[nt][0], sacc[nt][1]));
            mx1 = fmaxf(mx1, fmaxf(sacc[nt][2], sacc[nt][3]));
        }
        mx0 = fmaxf(mx0, __shfl_xor_sync(0xffffffffu, mx0, 1));
        mx0 = fmaxf(mx0, __shfl_xor_sync(0xffffffffu, mx0, 2));
        mx1 = fmaxf(mx1, __shfl_xor_sync(0xffffffffu, mx1, 1));
        mx1 = fmaxf(mx1, __shfl_xor_sync(0xffffffffu, mx1, 2));
        float mn0 = fmaxf(m0, mx0), mn1 = fmaxf(m1, mx1);
        float al0 = __expf(m0 - mn0), al1 = __expf(m1 - mn1);
        float rs0 = 0.f, rs1 = 0.f;
        #pragma unroll
        for (int nt = 0; nt < 8; nt++) {
            float p0 = __expf(sacc[nt][0] - mn0); sacc[nt][0] = p0; rs0 += p0;
            float p1 = __expf(sacc[nt][1] - mn0); sacc[nt][1] = p1; rs0 += p1;
            float p2 = __expf(sacc[nt][2] - mn1); sacc[nt][2] = p2; rs1 += p2;
            float p3 = __expf(sacc[nt][3] - mn1); sacc[nt][3] = p3; rs1 += p3;
        }
        rs0 += __shfl_xor_sync(0xffffffffu, rs0, 1);
        rs0 += __shfl_xor_sync(0xffffffffu, rs0, 2);
        rs1 += __shfl_xor_sync(0xffffffffu, rs1, 1);
        rs1 += __shfl_xor_sync(0xffffffffu, rs1, 2);
        l0 = l0 * al0 + rs0;
        l1 = l1 * al1 + rs1;
        m0 = mn0; m1 = mn1;
        #pragma unroll
        for (int nt = 0; nt < 8; nt++) {
            oacc[nt][0] *= al0; oacc[nt][1] *= al0;
            oacc[nt][2] *= al1; oacc[nt][3] *= al1;
        }

        #pragma unroll
        for (int kt = 0; kt < 4; kt++) {
            unsigned pa[4];
            pa[0] = packh2(sacc[2*kt][0],     sacc[2*kt][1]);
            pa[1] = packh2(sacc[2*kt][2],     sacc[2*kt][3]);
            pa[2] = packh2(sacc[2*kt + 1][0], sacc[2*kt + 1][1]);
            pa[3] = packh2(sacc[2*kt + 1][2], sacc[2*kt + 1][3]);
            #pragma unroll
            for (int p = 0; p < 4; p++) {
                unsigned r0, r1, r2, r3;
                ldm_x4_t(r0, r1, r2, r3, vb + ((kt*16 + lmr) * 72 + p*16 + lmk) * 2);
                unsigned b0[2] = { r0, r1 }, b1[2] = { r2, r3 };
                mma16h(oacc[2*p],   pa, b0);
                mma16h(oacc[2*p+1], pa, b1);
            }
        }
    }

    float inv0 = 1.f / l0, inv1 = 1.f / l1;
    size_t r0 = ((size_t)b * Tt + t_r0) * DM + h * DH;
    size_t r1 = ((size_t)b * Tt + t_r1) * DM + h * DH;
    #pragma unroll
    for (int nt = 0; nt < 8; nt++) {
        int d = nt*8 + q*2;
        g_ctxh[r0 + d]     = __float2half_rn(oacc[nt][0] * inv0);
        g_ctxh[r0 + d + 1] = __float2half_rn(oacc[nt][1] * inv0);
        g_ctxh[r1 + d]     = __float2half_rn(oacc[nt][2] * inv1);
        g_ctxh[r1 + d + 1] = __float2half_rn(oacc[nt][3] * inv1);
    }
}

// ---------------- launch -------------------------------------------------------------------
extern "C" void kernel_launch(void* const* d_in, const int* in_sizes, int n_in,
                              void* d_out, int out_size) {
    const float* x  = (const float*)d_in[0];
    const float* wq = (const float*)d_in[1];
    const float* wk = (const float*)d_in[2];
    const float* wv = (const float*)d_in[3];
    const float* wp = (const float*)d_in[4];
    float* out = (float*)d_out;

    cudaFuncSetAttribute(k_gemm_qkv, cudaFuncAttributeMaxDynamicSharedMemorySize, GSMEM_B);
    cudaFuncSetAttribute(k_proj,     cudaFuncAttributeMaxDynamicSharedMemorySize, GSMEM_B);

    k_rtab   <<<(Tt * 32) / 256, 256>>>();
    k_split_x<<<(size_t)(Bb*Tt*DM) / 1024, 256>>>((const float4*)x);
    k_split_w<<<10240, 256>>>((const float4*)wq, (const float4*)wk,
                              (const float4*)wv, (const float4*)wp);

    k_gemm_qkv<<<1024 + 136, 256, GSMEM_B>>>();

    k_flash<<<dim3(Tt / 128, Bb * NH), 256>>>();

    k_proj<<<dim3(DM / 128, (Bb * Tt) / 128), 256, GSMEM_B>>>(out);
}

// round 16
// speedup vs baseline: 1.0848x; 1.0680x over previous
#include <cuda_runtime.h>
#include <cuda_fp16.h>
#include <math.h>

#define Bb 2
#define Tt 4096
#define DM 2048
#define NH 32
#define NKV 8
#define DH 64
#define SS 1028
#define SINKN 4
#define POS_SHIFT 3068

// ---------------- scratch (16B-aligned) --------------------------------------------
__device__ __align__(16) __half g_xh  [(size_t)Bb*Tt*DM];
__device__ __align__(16) __half g_wqh [(size_t)DM*DM];
__device__ __align__(16) __half g_wkvh[(size_t)1024*DM];
__device__ __align__(16) __half g_wph [(size_t)DM*DM];
__device__ __align__(16) __half g_ctxh[(size_t)Bb*Tt*DM];
__device__ __align__(16) __half g_Qh [(size_t)Bb*NH*Tt*DH];
__device__ __align__(16) __half g_Kh [(size_t)Bb*NKV*SS*DH];
__device__ __align__(16) __half g_vtm[(size_t)Bb*SS*512];
__device__ __align__(16) float2 g_rtab[(size_t)Tt*32];

// ---------------- helpers ------------------------------------------------------------
__device__ __forceinline__ void mma16h(float c[4], const unsigned a[4], const unsigned b[2]) {
    asm volatile("mma.sync.aligned.m16n8k16.row.col.f32.f16.f16.f32 "
        "{%0,%1,%2,%3},{%4,%5,%6,%7},{%8,%9},{%0,%1,%2,%3};"
        : "+f"(c[0]), "+f"(c[1]), "+f"(c[2]), "+f"(c[3])
        : "r"(a[0]), "r"(a[1]), "r"(a[2]), "r"(a[3]), "r"(b[0]), "r"(b[1]));
}
__device__ __forceinline__ void ldm_x4(unsigned &r0, unsigned &r1, unsigned &r2, unsigned &r3,
                                       unsigned addr) {
    asm volatile("ldmatrix.sync.aligned.m8n8.x4.shared.b16 {%0,%1,%2,%3}, [%4];"
        : "=r"(r0), "=r"(r1), "=r"(r2), "=r"(r3) : "r"(addr));
}
__device__ __forceinline__ void ldm_x4_t(unsigned &r0, unsigned &r1, unsigned &r2, unsigned &r3,
                                         unsigned addr) {
    asm volatile("ldmatrix.sync.aligned.m8n8.x4.trans.shared.b16 {%0,%1,%2,%3}, [%4];"
        : "=r"(r0), "=r"(r1), "=r"(r2), "=r"(r3) : "r"(addr));
}
__device__ __forceinline__ unsigned packh2(float lo, float hi) {
    __half2 h = __floats2half2_rn(lo, hi);
    return *reinterpret_cast<unsigned*>(&h);
}
__device__ __forceinline__ unsigned smem_u32(const void* p) {
    return (unsigned)__cvta_generic_to_shared(p);
}
__device__ __forceinline__ void cpa16(unsigned dst, const void* src) {
    asm volatile("cp.async.cg.shared.global [%0], [%1], 16;" :: "r"(dst), "l"(src));
}
__device__ __forceinline__ void cpa16z(unsigned dst, const void* src, unsigned sz) {
    asm volatile("cp.async.cg.shared.global [%0], [%1], 16, %2;" :: "r"(dst), "l"(src), "r"(sz));
}
__device__ __forceinline__ uint2 pack4(float4 v) {
    __half2 h0 = __floats2half2_rn(v.x, v.y);
    __half2 h1 = __floats2half2_rn(v.z, v.w);
    return make_uint2(*reinterpret_cast<unsigned*>(&h0), *reinterpret_cast<unsigned*>(&h1));
}

// ---------------- RoPE trig table ------------------------------------------------------
__global__ void k_rtab() {
    int idx = blockIdx.x * 256 + threadIdx.x;
    int i = idx & 31, t = idx >> 5;
    double inv = pow(10000.0, -(double)i / 32.0);
    double ang = (double)t * inv;
    g_rtab[idx] = make_float2((float)cos(ang), (float)sin(ang));
}

// ---------------- split kernels ----------------------------------------------------------
__global__ void k_split_x(const float4* __restrict__ s) {
    size_t i = (size_t)blockIdx.x * blockDim.x + threadIdx.x;
    *(uint2*)&g_xh[i * 4] = pack4(s[i]);
}
__global__ void k_split_w(const float4* __restrict__ wq, const float4* __restrict__ wk,
                          const float4* __restrict__ wv, const float4* __restrict__ wp) {
    size_t i = (size_t)blockIdx.x * 256 + threadIdx.x;
    const size_t NQ = (size_t)DM * DM / 4;
    const size_t NK = (size_t)512 * DM / 4;
    if (i < NQ) {
        *(uint2*)&g_wqh[i * 4] = pack4(wq[i]);
    } else if (i < NQ + NK) {
        size_t j = i - NQ;
        *(uint2*)&g_wkvh[j * 4] = pack4(wk[j]);
    } else if (i < NQ + 2 * NK) {
        size_t j = i - NQ - NK;
        *(uint2*)&g_wkvh[(size_t)512 * DM + j * 4] = pack4(wv[j]);
    } else {
        size_t j = i - NQ - 2 * NK;
        *(uint2*)&g_wph[j * 4] = pack4(wp[j]);
    }
}

// ---------------- fp16 GEMM core, BK=32, 2-stage cp.async (round-13 proven) --------------
#define SK3 40

template<int MODE>
__device__ __forceinline__ void gemm_core(int bxx, int byy, float* __restrict__ C,
                                          int M, int N, int K)
{
    const __half* A_ = (MODE == 2) ? g_ctxh : g_xh;
    const __half* W_ = (MODE == 0) ? g_wqh : (MODE == 1) ? g_wkvh : g_wph;

    __shared__ __align__(16) __half sm[2][2][128 * SK3];   // 40 KB
    int tid = threadIdx.x, lane = tid & 31, wid = tid >> 5;
    int wm = wid >> 1, wn = wid & 1, gp = lane >> 2, q = lane & 3;
    int bm = byy * 128, bn = bxx * 128;
    int lmr = lane & 15, lmk = (lane >> 4) * 8;

    float acc[2][8][4];
    #pragma unroll
    for (int mt = 0; mt < 2; mt++)
        #pragma unroll
        for (int nt = 0; nt < 8; nt++)
            #pragma unroll
            for (int i = 0; i < 4; i++) acc[mt][nt][i] = 0.f;

    int row0 = tid >> 2, seg = (tid & 3) * 8;
    const __half* gaa[2];
    const __half* gbb[2];
    unsigned sa[2][2], sb[2][2];
    #pragma unroll
    for (int j = 0; j < 2; j++) {
        int r = row0 + j * 64;
        int arow = bm + r; if (arow > M - 1) arow = M - 1;
        int brow = bn + r; if (brow > N - 1) brow = N - 1;
        if (MODE == 1) {
            int ab = arow / SS, aj = arow % SS;
            int pos = (aj < SINKN) ? aj : aj + POS_SHIFT;
            gaa[j] = A_ + ((size_t)ab * Tt + pos) * DM + seg;
        } else {
            gaa[j] = A_ + (size_t)arow * K + seg;
        }
        gbb[j] = W_ + (size_t)brow * K + seg;
        #pragma unroll
        for (int s = 0; s < 2; s++) {
            sa[s][j] = smem_u32(&sm[s][0][r * SK3 + seg]);
            sb[s][j] = smem_u32(&sm[s][1][r * SK3 + seg]);
        }
    }

    int iters = K / 32;
    #pragma unroll
    for (int j = 0; j < 2; j++) { cpa16(sa[0][j], gaa[j]); cpa16(sb[0][j], gbb[j]); }
    asm volatile("cp.async.commit_group;");

    for (int i = 0; i < iters; i++) {
        asm volatile("cp.async.wait_group 0;");
        __syncthreads();
        if (i + 1 < iters) {
            int st = (i + 1) & 1, k0 = (i + 1) * 32;
            #pragma unroll
            for (int j = 0; j < 2; j++) {
                cpa16(sa[st][j], gaa[j] + k0);
                cpa16(sb[st][j], gbb[j] + k0);
            }
            asm volatile("cp.async.commit_group;");
        }

        int cur = i & 1;
        unsigned abase = smem_u32(&sm[cur][0][0]);
        unsigned bbase = smem_u32(&sm[cur][1][0]);

        unsigned a[2][2][4];
        #pragma unroll
        for (int mt = 0; mt < 2; mt++)
            #pragma unroll
            for (int kk = 0; kk < 2; kk++)
                ldm_x4(a[mt][kk][0], a[mt][kk][1], a[mt][kk][2], a[mt][kk][3],
                       abase + ((wm*32 + mt*16 + lmr) * SK3 + kk*16 + lmk) * 2);

        #pragma unroll
        for (int p = 0; p < 4; p++) {
            #pragma unroll
            for (int kk = 0; kk < 2; kk++) {
                unsigned r0, r1, r2, r3;
                ldm_x4(r0, r1, r2, r3,
                       bbase + ((wn*64 + p*16 + lmr) * SK3 + kk*16 + lmk) * 2);
                unsigned b0[2] = { r0, r2 }, b1[2] = { r1, r3 };
                mma16h(acc[0][2*p],   a[0][kk], b0);
                mma16h(acc[1][2*p],   a[1][kk], b0);
                mma16h(acc[0][2*p+1], a[0][kk], b1);
                mma16h(acc[1][2*p+1], a[1][kk], b1);
            }
        }
    }

    // ---------------- epilogues ----------------
    int cb = bn + wn * 64;
    if (MODE == 0) {
        int h = cb >> 6;
        #pragma unroll
        for (int mt = 0; mt < 2; mt++) {
            int r = bm + wm * 32 + mt * 16 + gp;
            #pragma unroll
            for (int half_ = 0; half_ < 2; half_++) {
                int rr = r + half_ * 8;
                int b = rr >> 12, t = rr & 4095;
                size_t o = (((size_t)b * NH + h) * Tt + t) * DH;
                #pragma unroll
                for (int nt = 0; nt < 4; nt++) {
                    int i2 = nt * 8 + q * 2;
                    float x1a = acc[mt][nt][2*half_],     x1b = acc[mt][nt][2*half_ + 1];
                    float x2a = acc[mt][nt + 4][2*half_], x2b = acc[mt][nt + 4][2*half_ + 1];
                    float2 ca  = g_rtab[t * 32 + i2];
                    float2 cbv = g_rtab[t * 32 + i2 + 1];
                    *(unsigned*)&g_Qh[o + i2] =
                        packh2(0.125f * (x1a * ca.x - x2a * ca.y),
                               0.125f * (x1b * cbv.x - x2b * cbv.y));
                    *(unsigned*)&g_Qh[o + i2 + 32] =
                        packh2(0.125f * (x2a * ca.x + x1a * ca.y),
                               0.125f * (x2b * cbv.x + x1b * cbv.y));
                }
            }
        }
    } else if (MODE == 1) {
        int hb = cb >> 6;
        #pragma unroll
        for (int mt = 0; mt < 2; mt++) {
            int r = bm + wm * 32 + mt * 16 + gp;
            #pragma unroll
            for (int half_ = 0; half_ < 2; half_++) {
                int rr = r + half_ * 8;
                if (rr >= M) continue;
                int b = (rr >= SS) ? 1 : 0;
                int j = rr - b * SS;
                if (hb < 8) {
                    int pos = (j < SINKN) ? j : j + POS_SHIFT;
                    size_t o = (((size_t)b * NKV + hb) * SS + j) * DH;
                    #pragma unroll
                    for (int nt = 0; nt < 4; nt++) {
                        int i2 = nt * 8 + q * 2;
                        float x1a = acc[mt][nt][2*half_],     x1b = acc[mt][nt][2*half_ + 1];
                        float x2a = acc[mt][nt + 4][2*half_], x2b = acc[mt][nt + 4][2*half_ + 1];
                        float2 ca  = g_rtab[pos * 32 + i2];
                        float2 cbv = g_rtab[pos * 32 + i2 + 1];
                        *(unsigned*)&g_Kh[o + i2] =
                            packh2(x1a * ca.x - x2a * ca.y, x1b * cbv.x - x2b * cbv.y);
                        *(unsigned*)&g_Kh[o + i2 + 32] =
                            packh2(x2a * ca.x + x1a * ca.y, x2b * cbv.x + x1b * cbv.y);
                    }
                } else {
                    size_t o = ((size_t)b * SS + j) * 512 + (hb - 8) * 64;
                    #pragma unroll
                    for (int nt = 0; nt < 8; nt++) {
                        int d = nt * 8 + q * 2;
                        *(unsigned*)&g_vtm[o + d] =
                            packh2(acc[mt][nt][2*half_], acc[mt][nt][2*half_ + 1]);
                    }
                }
            }
        }
    } else {
        #pragma unroll
        for (int mt = 0; mt < 2; mt++) {
            int r = bm + wm * 32 + mt * 16 + gp;
            #pragma unroll
            for (int nt = 0; nt < 8; nt++) {
                int cc = cb + nt * 8 + q * 2;
                *(float2*)&C[(size_t)r * N + cc]     = make_float2(acc[mt][nt][0], acc[mt][nt][1]);
                *(float2*)&C[(size_t)(r+8) * N + cc] = make_float2(acc[mt][nt][2], acc[mt][nt][3]);
            }
        }
    }
}

// merged Q + KV projection (1160 blocks; KV tiles dispatched FIRST)
__global__ void __launch_bounds__(256, 2) k_gemm_qkv() {
    int bid = blockIdx.x;
    if (bid < 136) {
        gemm_core<1>(bid & 7, bid >> 3, nullptr, Bb * SS, 1024, DM);
    } else {
        int r = bid - 136;
        gemm_core<0>(r & 15, r >> 4, nullptr, Bb * Tt, DM, DM);
    }
}
__global__ void __launch_bounds__(256, 2) k_proj(float* __restrict__ out) {
    gemm_core<2>(blockIdx.x, blockIdx.y, out, Bb * Tt, DM, DM);
}

// ---------------- fused flash attention (heavy blocks first) ------------------------------
__global__ void __launch_bounds__(256, 2) k_flash() {
    __shared__ __align__(16) __half Ks[2][64 * 72];
    __shared__ __align__(16) __half Vs[2][64 * 72];
    int tid = threadIdx.x, lane = tid & 31, wid = tid >> 5;
    int gp = lane >> 2, q = lane & 3;
    int lmr = lane & 15, lmk = (lane >> 4) * 8;
    int bx = gridDim.x - 1 - blockIdx.x;     // heavy (large t0) blocks scheduled first
    int t0 = bx * 128;
    int z = blockIdx.y;
    int b = z >> 5, h = z & 31, kvh = h >> 2;
    int bk = b * NKV + kvh;
    const __half* Qp = g_Qh + (size_t)z * Tt * DH;
    const __half* Kp = g_Kh + (size_t)bk * SS * DH;
    const __half* Vp = g_vtm + (size_t)b * SS * 512 + kvh * 64;

    int t_r0 = t0 + wid * 16 + gp;
    int t_r1 = t_r0 + 8;
    int warp_tmin = t0 + wid * 16;
    int s_end = min(SS, t0 + 128);
    int ntiles = (s_end + 63) >> 6;

    unsigned kbs[2] = { smem_u32(Ks[0]), smem_u32(Ks[1]) };
    unsigned vbs[2] = { smem_u32(Vs[0]), smem_u32(Vs[1]) };

    auto load_tile = [&](int s0, int st) {
        #pragma unroll
        for (int c = 0; c < 2; c++) {
            int f = c * 256 + tid;
            int r = f >> 3, sg = (f & 7) * 8;
            int srow = s0 + r;
            unsigned sz = (srow < SS) ? 16u : 0u;
            cpa16z(kbs[st] + (r * 72 + sg) * 2, Kp + (size_t)srow * DH + sg, sz);
            cpa16z(vbs[st] + (r * 72 + sg) * 2, Vp + (size_t)srow * 512 + sg, sz);
        }
        asm volatile("cp.async.commit_group;");
    };

    unsigned qa[4][4];
    {
        const unsigned* uQ0 = (const unsigned*)(Qp + (size_t)t_r0 * DH);
        const unsigned* uQ1 = (const unsigned*)(Qp + (size_t)t_r1 * DH);
        #pragma unroll
        for (int kk = 0; kk < 4; kk++) {
            qa[kk][0] = uQ0[kk * 8 + q];
            qa[kk][1] = uQ1[kk * 8 + q];
            qa[kk][2] = uQ0[kk * 8 + q + 4];
            qa[kk][3] = uQ1[kk * 8 + q + 4];
        }
    }

    float oacc[8][4];
    #pragma unroll
    for (int nt = 0; nt < 8; nt++)
        #pragma unroll
        for (int i = 0; i < 4; i++) oacc[nt][i] = 0.f;
    float m0 = -1e30f, m1 = -1e30f, l0 = 0.f, l1 = 0.f;

    load_tile(0, 0);

    for (int ti = 0; ti < ntiles; ti++) {
        int s0 = ti * 64;
        asm volatile("cp.async.wait_group 0;");
        __syncthreads();
        if (ti + 1 < ntiles) load_tile((ti + 1) * 64, (ti + 1) & 1);

        int st = ti & 1;
        unsigned kb = kbs[st], vb = vbs[st];

        float sacc[8][4];
        #pragma unroll
        for (int nt = 0; nt < 8; nt++)
            #pragma unroll
            for (int i = 0; i < 4; i++) sacc[nt][i] = 0.f;
        #pragma unroll
        for (int kk = 0; kk < 4; kk++) {
            #pragma unroll
            for (int p = 0; p < 4; p++) {
                unsigned r0, r1, r2, r3;
                ldm_x4(r0, r1, r2, r3, kb + ((p*16 + lmr) * 72 + kk*16 + lmk) * 2);
                unsigned b0[2] = { r0, r2 }, b1[2] = { r1, r3 };
                mma16h(sacc[2*p],   qa[kk], b0);
                mma16h(sacc[2*p+1], qa[kk], b1);
            }
        }

        bool nomask = (s0 + 63 <= warp_tmin) && (s0 + 64 <= SS);
        if (!nomask) {
            #pragma unroll
            for (int nt = 0; nt < 8; nt++) {
                int j = s0 + nt*8 + q*2;
                if (!(j     <= t_r0 && j     < SS)) sacc[nt][0] = -1e30f;
                if (!(j + 1 <= t_r0 && j + 1 < SS)) sacc[nt][1] = -1e30f;
                if (!(j     <= t_r1 && j     < SS)) sacc[nt][2] = -1e30f;
                if (!(j + 1 <= t_r1 && j + 1 < SS)) sacc[nt][3] = -1e30f;
            }
        }

        float mx0 = -1e30f, mx1 = -1e30f;
        #pragma unroll
        for (int nt = 0; nt < 8; nt++) {
            mx0 = fmaxf(mx0, fmaxf(sacc[nt][0], sacc[nt][1]));
            mx1 = fmaxf(mx1, fmaxf(sacc[nt][2], sacc[nt][3]));
        }
        mx0 = fmaxf(mx0, __shfl_xor_sync(0xffffffffu, mx0, 1));
        mx0 = fmaxf(mx0, __shfl_xor_sync(0xffffffffu, mx0, 2));
        mx1 = fmaxf(mx1, __shfl_xor_sync(0xffffffffu, mx1, 1));
        mx1 = fmaxf(mx1, __shfl_xor_sync(0xffffffffu, mx1, 2));
        float mn0 = fmaxf(m0, mx0), mn1 = fmaxf(m1, mx1);
        float al0 = __expf(m0 - mn0), al1 = __expf(m1 - mn1);
        float rs0 = 0.f, rs1 = 0.f;
        #pragma unroll
        for (int nt = 0; nt < 8; nt++) {
            float p0 = __expf(sacc[nt][0] - mn0); sacc[nt][0] = p0; rs0 += p0;
            float p1 = __expf(sacc[nt][1] - mn0); sacc[nt][1] = p1; rs0 += p1;
            float p2 = __expf(sacc[nt][2] - mn1); sacc[nt][2] = p2; rs1 += p2;
            float p3 = __expf(sacc[nt][3] - mn1); sacc[nt][3] = p3; rs1 += p3;
        }
        rs0 += __shfl_xor_sync(0xffffffffu, rs0, 1);
        rs0 += __shfl_xor_sync(0xffffffffu, rs0, 2);
        rs1 += __shfl_xor_sync(0xffffffffu, rs1, 1);
        rs1 += __shfl_xor_sync(0xffffffffu, rs1, 2);
        l0 = l0 * al0 + rs0;
        l1 = l1 * al1 + rs1;
        m0 = mn0; m1 = mn1;
        #pragma unroll
        for (int nt = 0; nt < 8; nt++) {
            oacc[nt][0] *= al0; oacc[nt][1] *= al0;
            oacc[nt][2] *= al1; oacc[nt][3] *= al1;
        }

        #pragma unroll
        for (int kt = 0; kt < 4; kt++) {
            unsigned pa[4];
            pa[0] = packh2(sacc[2*kt][0],     sacc[2*kt][1]);
            pa[1] = packh2(sacc[2*kt][2],     sacc[2*kt][3]);
            pa[2] = packh2(sacc[2*kt + 1][0], sacc[2*kt + 1][1]);
            pa[3] = packh2(sacc[2*kt + 1][2], sacc[2*kt + 1][3]);
            #pragma unroll
            for (int p = 0; p < 4; p++) {
                unsigned r0, r1, r2, r3;
                ldm_x4_t(r0, r1, r2, r3, vb + ((kt*16 + lmr) * 72 + p*16 + lmk) * 2);
                unsigned b0[2] = { r0, r1 }, b1[2] = { r2, r3 };
                mma16h(oacc[2*p],   pa, b0);
                mma16h(oacc[2*p+1], pa, b1);
            }
        }
    }

    float inv0 = 1.f / l0, inv1 = 1.f / l1;
    size_t r0 = ((size_t)b * Tt + t_r0) * DM + h * DH;
    size_t r1 = ((size_t)b * Tt + t_r1) * DM + h * DH;
    #pragma unroll
    for (int nt = 0; nt < 8; nt++) {
        int d = nt*8 + q*2;
        g_ctxh[r0 + d]     = __float2half_rn(oacc[nt][0] * inv0);
        g_ctxh[r0 + d + 1] = __float2half_rn(oacc[nt][1] * inv0);
        g_ctxh[r1 + d]     = __float2half_rn(oacc[nt][2] * inv1);
        g_ctxh[r1 + d + 1] = __float2half_rn(oacc[nt][3] * inv1);
    }
}

// ---------------- launch -------------------------------------------------------------------
extern "C" void kernel_launch(void* const* d_in, const int* in_sizes, int n_in,
                              void* d_out, int out_size) {
    const float* x  = (const float*)d_in[0];
    const float* wq = (const float*)d_in[1];
    const float* wk = (const float*)d_in[2];
    const float* wv = (const float*)d_in[3];
    const float* wp = (const float*)d_in[4];
    float* out = (float*)d_out;

    k_rtab   <<<(Tt * 32) / 256, 256>>>();
    k_split_x<<<(size_t)(Bb*Tt*DM) / 1024, 256>>>((const float4*)x);
    k_split_w<<<10240, 256>>>((const float4*)wq, (const float4*)wk,
                              (const float4*)wv, (const float4*)wp);

    k_gemm_qkv<<<1024 + 136, 256>>>();

    k_flash<<<dim3(Tt / 128, Bb * NH), 256>>>();

    k_proj<<<dim3(DM / 128, (Bb * Tt) / 128), 256>>>(out);
}

// round 17
// speedup vs baseline: 1.1210x; 1.0333x over previous
#include <cuda_runtime.h>
#include <cuda_fp16.h>
#include <math.h>

#define Bb 2
#define Tt 4096
#define DM 2048
#define NH 32
#define NKV 8
#define DH 64
#define SS 1028
#define SINKN 4
#define POS_SHIFT 3068

// ---------------- scratch (16B-aligned) --------------------------------------------
__device__ __align__(16) __half g_xh  [(size_t)Bb*Tt*DM];
__device__ __align__(16) __half g_wqh [(size_t)DM*DM];
__device__ __align__(16) __half g_wkvh[(size_t)1024*DM];
__device__ __align__(16) __half g_wph [(size_t)DM*DM];
__device__ __align__(16) __half g_ctxh[(size_t)Bb*Tt*DM];
__device__ __align__(16) __half g_Qh [(size_t)Bb*NH*Tt*DH];
__device__ __align__(16) __half g_Kh [(size_t)Bb*NKV*SS*DH];
__device__ __align__(16) __half g_vtm[(size_t)Bb*SS*512];
__device__ __align__(16) float2 g_rtab[(size_t)Tt*32];

// ---------------- helpers ------------------------------------------------------------
__device__ __forceinline__ void mma16h(float c[4], const unsigned a[4], const unsigned b[2]) {
    asm volatile("mma.sync.aligned.m16n8k16.row.col.f32.f16.f16.f32 "
        "{%0,%1,%2,%3},{%4,%5,%6,%7},{%8,%9},{%0,%1,%2,%3};"
        : "+f"(c[0]), "+f"(c[1]), "+f"(c[2]), "+f"(c[3])
        : "r"(a[0]), "r"(a[1]), "r"(a[2]), "r"(a[3]), "r"(b[0]), "r"(b[1]));
}
__device__ __forceinline__ void ldm_x4(unsigned &r0, unsigned &r1, unsigned &r2, unsigned &r3,
                                       unsigned addr) {
    asm volatile("ldmatrix.sync.aligned.m8n8.x4.shared.b16 {%0,%1,%2,%3}, [%4];"
        : "=r"(r0), "=r"(r1), "=r"(r2), "=r"(r3) : "r"(addr));
}
__device__ __forceinline__ void ldm_x4_t(unsigned &r0, unsigned &r1, unsigned &r2, unsigned &r3,
                                         unsigned addr) {
    asm volatile("ldmatrix.sync.aligned.m8n8.x4.trans.shared.b16 {%0,%1,%2,%3}, [%4];"
        : "=r"(r0), "=r"(r1), "=r"(r2), "=r"(r3) : "r"(addr));
}
__device__ __forceinline__ unsigned packh2(float lo, float hi) {
    __half2 h = __floats2half2_rn(lo, hi);
    return *reinterpret_cast<unsigned*>(&h);
}
__device__ __forceinline__ unsigned smem_u32(const void* p) {
    return (unsigned)__cvta_generic_to_shared(p);
}
__device__ __forceinline__ void cpa16(unsigned dst, const void* src) {
    asm volatile("cp.async.cg.shared.global [%0], [%1], 16;" :: "r"(dst), "l"(src));
}
__device__ __forceinline__ void cpa16z(unsigned dst, const void* src, unsigned sz) {
    asm volatile("cp.async.cg.shared.global [%0], [%1], 16, %2;" :: "r"(dst), "l"(src), "r"(sz));
}
__device__ __forceinline__ uint2 pack4(float4 v) {
    __half2 h0 = __floats2half2_rn(v.x, v.y);
    __half2 h1 = __floats2half2_rn(v.z, v.w);
    return make_uint2(*reinterpret_cast<unsigned*>(&h0), *reinterpret_cast<unsigned*>(&h1));
}

// ---------------- merged prep: split x, split weights, rope table -----------------------
#define NXB 16384            // x float4 blocks
#define NWB 10240            // weight float4 blocks
__global__ void k_prep(const float4* __restrict__ x,
                       const float4* __restrict__ wq, const float4* __restrict__ wk,
                       const float4* __restrict__ wv, const float4* __restrict__ wp) {
    int bid = blockIdx.x;
    if (bid < NXB) {
        size_t i = (size_t)bid * 256 + threadIdx.x;
        *(uint2*)&g_xh[i * 4] = pack4(x[i]);
    } else if (bid < NXB + NWB) {
        size_t i = (size_t)(bid - NXB) * 256 + threadIdx.x;
        const size_t NQ = (size_t)DM * DM / 4;
        const size_t NK = (size_t)512 * DM / 4;
        if (i < NQ) {
            *(uint2*)&g_wqh[i * 4] = pack4(wq[i]);
        } else if (i < NQ + NK) {
            size_t j = i - NQ;
            *(uint2*)&g_wkvh[j * 4] = pack4(wk[j]);
        } else if (i < NQ + 2 * NK) {
            size_t j = i - NQ - NK;
            *(uint2*)&g_wkvh[(size_t)512 * DM + j * 4] = pack4(wv[j]);
        } else {
            size_t j = i - NQ - 2 * NK;
            *(uint2*)&g_wph[j * 4] = pack4(wp[j]);
        }
    } else {
        int idx = (bid - NXB - NWB) * 256 + threadIdx.x;   // Tt*32 items
        int i = idx & 31, t = idx >> 5;
        double inv = pow(10000.0, -(double)i / 32.0);
        double ang = (double)t * inv;
        g_rtab[idx] = make_float2((float)cos(ang), (float)sin(ang));
    }
}

// ---------------- fp16 GEMM core, BK=64, 2-stage cp.async, dynamic smem ------------------
#define SK4 72                       // smem row stride (64 + 8 pad halfs)
#define STG_H (2 * 128 * SK4)        // halfs per stage (A+B planes) = 18432
#define GSMEM4 (2 * STG_H * 2)       // 73728 bytes

template<int MODE>
__device__ __forceinline__ void gemm_core(int bxx, int byy, float* __restrict__ C,
                                          int M, int N, int K)
{
    const __half* A_ = (MODE == 2) ? g_ctxh : g_xh;
    const __half* W_ = (MODE == 0) ? g_wqh : (MODE == 1) ? g_wkvh : g_wph;

    extern __shared__ __align__(16) __half dsm[];
    int tid = threadIdx.x, lane = tid & 31, wid = tid >> 5;
    int wm = wid >> 1, wn = wid & 1, gp = lane >> 2, q = lane & 3;
    int bm = byy * 128, bn = bxx * 128;
    int lmr = lane & 15, lmk = (lane >> 4) * 8;

    float acc[2][8][4];
    #pragma unroll
    for (int mt = 0; mt < 2; mt++)
        #pragma unroll
        for (int nt = 0; nt < 8; nt++)
            #pragma unroll
            for (int i = 0; i < 4; i++) acc[mt][nt][i] = 0.f;

    // loader: 4 rows per plane per thread: row = (tid>>3) + j*32, seg = (tid&7)*8 halfs
    int row0 = tid >> 3, seg = (tid & 7) * 8;
    const __half* gaa[4];
    const __half* gbb[4];
    unsigned sa[2][4], sb[2][4];
    #pragma unroll
    for (int j = 0; j < 4; j++) {
        int r = row0 + j * 32;
        int arow = bm + r; if (arow > M - 1) arow = M - 1;
        int brow = bn + r; if (brow > N - 1) brow = N - 1;
        if (MODE == 1) {
            int ab = arow / SS, aj = arow % SS;
            int pos = (aj < SINKN) ? aj : aj + POS_SHIFT;
            gaa[j] = A_ + ((size_t)ab * Tt + pos) * DM + seg;
        } else {
            gaa[j] = A_ + (size_t)arow * K + seg;
        }
        gbb[j] = W_ + (size_t)brow * K + seg;
        #pragma unroll
        for (int s = 0; s < 2; s++) {
            sa[s][j] = smem_u32(&dsm[s * STG_H + r * SK4 + seg]);
            sb[s][j] = smem_u32(&dsm[s * STG_H + 128 * SK4 + r * SK4 + seg]);
        }
    }

    int iters = K / 64;
    #pragma unroll
    for (int j = 0; j < 4; j++) { cpa16(sa[0][j], gaa[j]); cpa16(sb[0][j], gbb[j]); }
    asm volatile("cp.async.commit_group;");

    for (int i = 0; i < iters; i++) {
        asm volatile("cp.async.wait_group 0;");
        __syncthreads();
        if (i + 1 < iters) {
            int st = (i + 1) & 1, k0 = (i + 1) * 64;
            #pragma unroll
            for (int j = 0; j < 4; j++) {
                cpa16(sa[st][j], gaa[j] + k0);
                cpa16(sb[st][j], gbb[j] + k0);
            }
            asm volatile("cp.async.commit_group;");
        }

        int cur = i & 1;
        unsigned abase = smem_u32(&dsm[cur * STG_H]);
        unsigned bbase = abase + 128 * SK4 * 2;

        #pragma unroll
        for (int kk = 0; kk < 4; kk++) {
            unsigned a[2][4];
            #pragma unroll
            for (int mt = 0; mt < 2; mt++)
                ldm_x4(a[mt][0], a[mt][1], a[mt][2], a[mt][3],
                       abase + ((wm*32 + mt*16 + lmr) * SK4 + kk*16 + lmk) * 2);
            #pragma unroll
            for (int p = 0; p < 4; p++) {
                unsigned r0, r1, r2, r3;
                ldm_x4(r0, r1, r2, r3,
                       bbase + ((wn*64 + p*16 + lmr) * SK4 + kk*16 + lmk) * 2);
                unsigned b0[2] = { r0, r2 }, b1[2] = { r1, r3 };
                mma16h(acc[0][2*p],   a[0], b0);
                mma16h(acc[1][2*p],   a[1], b0);
                mma16h(acc[0][2*p+1], a[0], b1);
                mma16h(acc[1][2*p+1], a[1], b1);
            }
        }
    }

    // ---------------- epilogues ----------------
    int cb = bn + wn * 64;
    if (MODE == 0) {
        int h = cb >> 6;
        #pragma unroll
        for (int mt = 0; mt < 2; mt++) {
            int r = bm + wm * 32 + mt * 16 + gp;
            #pragma unroll
            for (int half_ = 0; half_ < 2; half_++) {
                int rr = r + half_ * 8;
                int b = rr >> 12, t = rr & 4095;
                size_t o = (((size_t)b * NH + h) * Tt + t) * DH;
                #pragma unroll
                for (int nt = 0; nt < 4; nt++) {
                    int i2 = nt * 8 + q * 2;
                    float x1a = acc[mt][nt][2*half_],     x1b = acc[mt][nt][2*half_ + 1];
                    float x2a = acc[mt][nt + 4][2*half_], x2b = acc[mt][nt + 4][2*half_ + 1];
                    float2 ca  = g_rtab[t * 32 + i2];
                    float2 cbv = g_rtab[t * 32 + i2 + 1];
                    *(unsigned*)&g_Qh[o + i2] =
                        packh2(0.125f * (x1a * ca.x - x2a * ca.y),
                               0.125f * (x1b * cbv.x - x2b * cbv.y));
                    *(unsigned*)&g_Qh[o + i2 + 32] =
                        packh2(0.125f * (x2a * ca.x + x1a * ca.y),
                               0.125f * (x2b * cbv.x + x1b * cbv.y));
                }
            }
        }
    } else if (MODE == 1) {
        int hb = cb >> 6;
        #pragma unroll
        for (int mt = 0; mt < 2; mt++) {
            int r = bm + wm * 32 + mt * 16 + gp;
            #pragma unroll
            for (int half_ = 0; half_ < 2; half_++) {
                int rr = r + half_ * 8;
                if (rr >= M) continue;
                int b = (rr >= SS) ? 1 : 0;
                int j = rr - b * SS;
                if (hb < 8) {
                    int pos = (j < SINKN) ? j : j + POS_SHIFT;
                    size_t o = (((size_t)b * NKV + hb) * SS + j) * DH;
                    #pragma unroll
                    for (int nt = 0; nt < 4; nt++) {
                        int i2 = nt * 8 + q * 2;
                        float x1a = acc[mt][nt][2*half_],     x1b = acc[mt][nt][2*half_ + 1];
                        float x2a = acc[mt][nt + 4][2*half_], x2b = acc[mt][nt + 4][2*half_ + 1];
                        float2 ca  = g_rtab[pos * 32 + i2];
                        float2 cbv = g_rtab[pos * 32 + i2 + 1];
                        *(unsigned*)&g_Kh[o + i2] =
                            packh2(x1a * ca.x - x2a * ca.y, x1b * cbv.x - x2b * cbv.y);
                        *(unsigned*)&g_Kh[o + i2 + 32] =
                            packh2(x2a * ca.x + x1a * ca.y, x2b * cbv.x + x1b * cbv.y);
                    }
                } else {
                    size_t o = ((size_t)b * SS + j) * 512 + (hb - 8) * 64;
                    #pragma unroll
                    for (int nt = 0; nt < 8; nt++) {
                        int d = nt * 8 + q * 2;
                        *(unsigned*)&g_vtm[o + d] =
                            packh2(acc[mt][nt][2*half_], acc[mt][nt][2*half_ + 1]);
                    }
                }
            }
        }
    } else {
        #pragma unroll
        for (int mt = 0; mt < 2; mt++) {
            int r = bm + wm * 32 + mt * 16 + gp;
            #pragma unroll
            for (int nt = 0; nt < 8; nt++) {
                int cc = cb + nt * 8 + q * 2;
                *(float2*)&C[(size_t)r * N + cc]     = make_float2(acc[mt][nt][0], acc[mt][nt][1]);
                *(float2*)&C[(size_t)(r+8) * N + cc] = make_float2(acc[mt][nt][2], acc[mt][nt][3]);
            }
        }
    }
}

// merged Q + KV projection (1160 blocks; KV tiles dispatched FIRST)
__global__ void __launch_bounds__(256, 2) k_gemm_qkv() {
    int bid = blockIdx.x;
    if (bid < 136) {
        gemm_core<1>(bid & 7, bid >> 3, nullptr, Bb * SS, 1024, DM);
    } else {
        int r = bid - 136;
        gemm_core<0>(r & 15, r >> 4, nullptr, Bb * Tt, DM, DM);
    }
}
__global__ void __launch_bounds__(256, 2) k_proj(float* __restrict__ out) {
    gemm_core<2>(blockIdx.x, blockIdx.y, out, Bb * Tt, DM, DM);
}

// ---------------- fused flash attention (heavy blocks first) ------------------------------
__global__ void __launch_bounds__(256, 2) k_flash() {
    __shared__ __align__(16) __half Ks[2][64 * 72];
    __shared__ __align__(16) __half Vs[2][64 * 72];
    int tid = threadIdx.x, lane = tid & 31, wid = tid >> 5;
    int gp = lane >> 2, q = lane & 3;
    int lmr = lane & 15, lmk = (lane >> 4) * 8;
    int bx = gridDim.x - 1 - blockIdx.x;
    int t0 = bx * 128;
    int z = blockIdx.y;
    int b = z >> 5, h = z & 31, kvh = h >> 2;
    int bk = b * NKV + kvh;
    const __half* Qp = g_Qh + (size_t)z * Tt * DH;
    const __half* Kp = g_Kh + (size_t)bk * SS * DH;
    const __half* Vp = g_vtm + (size_t)b * SS * 512 + kvh * 64;

    int t_r0 = t0 + wid * 16 + gp;
    int t_r1 = t_r0 + 8;
    int warp_tmin = t0 + wid * 16;
    int s_end = min(SS, t0 + 128);
    int ntiles = (s_end + 63) >> 6;

    unsigned kbs[2] = { smem_u32(Ks[0]), smem_u32(Ks[1]) };
    unsigned vbs[2] = { smem_u32(Vs[0]), smem_u32(Vs[1]) };

    auto load_tile = [&](int s0, int st) {
        #pragma unroll
        for (int c = 0; c < 2; c++) {
            int f = c * 256 + tid;
            int r = f >> 3, sg = (f & 7) * 8;
            int srow = s0 + r;
            unsigned sz = (srow < SS) ? 16u : 0u;
            cpa16z(kbs[st] + (r * 72 + sg) * 2, Kp + (size_t)srow * DH + sg, sz);
            cpa16z(vbs[st] + (r * 72 + sg) * 2, Vp + (size_t)srow * 512 + sg, sz);
        }
        asm volatile("cp.async.commit_group;");
    };

    unsigned qa[4][4];
    {
        const unsigned* uQ0 = (const unsigned*)(Qp + (size_t)t_r0 * DH);
        const unsigned* uQ1 = (const unsigned*)(Qp + (size_t)t_r1 * DH);
        #pragma unroll
        for (int kk = 0; kk < 4; kk++) {
            qa[kk][0] = uQ0[kk * 8 + q];
            qa[kk][1] = uQ1[kk * 8 + q];
            qa[kk][2] = uQ0[kk * 8 + q + 4];
            qa[kk][3] = uQ1[kk * 8 + q + 4];
        }
    }

    float oacc[8][4];
    #pragma unroll
    for (int nt = 0; nt < 8; nt++)
        #pragma unroll
        for (int i = 0; i < 4; i++) oacc[nt][i] = 0.f;
    float m0 = -1e30f, m1 = -1e30f, l0 = 0.f, l1 = 0.f;

    load_tile(0, 0);

    for (int ti = 0; ti < ntiles; ti++) {
        int s0 = ti * 64;
        asm volatile("cp.async.wait_group 0;");
        __syncthreads();
        if (ti + 1 < ntiles) load_tile((ti + 1) * 64, (ti + 1) & 1);

        int st = ti & 1;
        unsigned kb = kbs[st], vb = vbs[st];

        float sacc[8][4];
        #pragma unroll
        for (int nt = 0; nt < 8; nt++)
            #pragma unroll
            for (int i = 0; i < 4; i++) sacc[nt][i] = 0.f;
        #pragma unroll
        for (int kk = 0; kk < 4; kk++) {
            #pragma unroll
            for (int p = 0; p < 4; p++) {
                unsigned r0, r1, r2, r3;
                ldm_x4(r0, r1, r2, r3, kb + ((p*16 + lmr) * 72 + kk*16 + lmk) * 2);
                unsigned b0[2] = { r0, r2 }, b1[2] = { r1, r3 };
                mma16h(sacc[2*p],   qa[kk], b0);
                mma16h(sacc[2*p+1], qa[kk], b1);
            }
        }

        bool nomask = (s0 + 63 <= warp_tmin) && (s0 + 64 <= SS);
        if (!nomask) {
            #pragma unroll
            for (int nt = 0; nt < 8; nt++) {
                int j = s0 + nt*8 + q*2;
                if (!(j     <= t_r0 && j     < SS)) sacc[nt][0] = -1e30f;
                if (!(j + 1 <= t_r0 && j + 1 < SS)) sacc[nt][1] = -1e30f;
                if (!(j     <= t_r1 && j     < SS)) sacc[nt][2] = -1e30f;
                if (!(j + 1 <= t_r1 && j + 1 < SS)) sacc[nt][3] = -1e30f;
            }
        }

        float mx0 = -1e30f, mx1 = -1e30f;
        #pragma unroll
        for (int nt = 0; nt < 8; nt++) {
            mx0 = fmaxf(mx0, fmaxf(sacc[nt][0], sacc[nt][1]));
            mx1 = fmaxf(mx1, fmaxf(sacc[nt][2], sacc[nt][3]));
        }
        mx0 = fmaxf(mx0, __shfl_xor_sync(0xffffffffu, mx0, 1));
        mx0 = fmaxf(mx0, __shfl_xor_sync(0xffffffffu, mx0, 2));
        mx1 = fmaxf(mx1, __shfl_xor_sync(0xffffffffu, mx1, 1));
        mx1 = fmaxf(mx1, __shfl_xor_sync(0xffffffffu, mx1, 2));
        float mn0 = fmaxf(m0, mx0), mn1 = fmaxf(m1, mx1);
        float al0 = __expf(m0 - mn0), al1 = __expf(m1 - mn1);
        float rs0 = 0.f, rs1 = 0.f;
        #pragma unroll
        for (int nt = 0; nt < 8; nt++) {
            float p0 = __expf(sacc[nt][0] - mn0); sacc[nt][0] = p0; rs0 += p0;
            float p1 = __expf(sacc[nt][1] - mn0); sacc[nt][1] = p1; rs0 += p1;
            float p2 = __expf(sacc[nt][2] - mn1); sacc[nt][2] = p2; rs1 += p2;
            float p3 = __expf(sacc[nt][3] - mn1); sacc[nt][3] = p3; rs1 += p3;
        }
        rs0 += __shfl_xor_sync(0xffffffffu, rs0, 1);
        rs0 += __shfl_xor_sync(0xffffffffu, rs0, 2);
        rs1 += __shfl_xor_sync(0xffffffffu, rs1, 1);
        rs1 += __shfl_xor_sync(0xffffffffu, rs1, 2);
        l0 = l0 * al0 + rs0;
        l1 = l1 * al1 + rs1;
        m0 = mn0; m1 = mn1;
        #pragma unroll
        for (int nt = 0; nt < 8; nt++) {
            oacc[nt][0] *= al0; oacc[nt][1] *= al0;
            oacc[nt][2] *= al1; oacc[nt][3] *= al1;
        }

        #pragma unroll
        for (int kt = 0; kt < 4; kt++) {
            unsigned pa[4];
            pa[0] = packh2(sacc[2*kt][0],     sacc[2*kt][1]);
            pa[1] = packh2(sacc[2*kt][2],     sacc[2*kt][3]);
            pa[2] = packh2(sacc[2*kt + 1][0], sacc[2*kt + 1][1]);
            pa[3] = packh2(sacc[2*kt + 1][2], sacc[2*kt + 1][3]);
            #pragma unroll
            for (int p = 0; p < 4; p++) {
                unsigned r0, r1, r2, r3;
                ldm_x4_t(r0, r1, r2, r3, vb + ((kt*16 + lmr) * 72 + p*16 + lmk) * 2);
                unsigned b0[2] = { r0, r1 }, b1[2] = { r2, r3 };
                mma16h(oacc[2*p],   pa, b0);
                mma16h(oacc[2*p+1], pa, b1);
            }
        }
    }

    float inv0 = 1.f / l0, inv1 = 1.f / l1;
    size_t r0 = ((size_t)b * Tt + t_r0) * DM + h * DH;
    size_t r1 = ((size_t)b * Tt + t_r1) * DM + h * DH;
    #pragma unroll
    for (int nt = 0; nt < 8; nt++) {
        int d = nt*8 + q*2;
        g_ctxh[r0 + d]     = __float2half_rn(oacc[nt][0] * inv0);
        g_ctxh[r0 + d + 1] = __float2half_rn(oacc[nt][1] * inv0);
        g_ctxh[r1 + d]     = __float2half_rn(oacc[nt][2] * inv1);
        g_ctxh[r1 + d + 1] = __float2half_rn(oacc[nt][3] * inv1);
    }
}

// ---------------- launch -------------------------------------------------------------------
extern "C" void kernel_launch(void* const* d_in, const int* in_sizes, int n_in,
                              void* d_out, int out_size) {
    const float* x  = (const float*)d_in[0];
    const float* wq = (const float*)d_in[1];
    const float* wk = (const float*)d_in[2];
    const float* wv = (const float*)d_in[3];
    const float* wp = (const float*)d_in[4];
    float* out = (float*)d_out;

    cudaFuncSetAttribute(k_gemm_qkv, cudaFuncAttributeMaxDynamicSharedMemorySize, GSMEM4);
    cudaFuncSetAttribute(k_proj,     cudaFuncAttributeMaxDynamicSharedMemorySize, GSMEM4);

    k_prep<<<NXB + NWB + (Tt * 32) / 256, 256>>>((const float4*)x, (const float4*)wq,
                                                 (const float4*)wk, (const float4*)wv,
                                                 (const float4*)wp);

    k_gemm_qkv<<<1024 + 136, 256, GSMEM4>>>();

    k_flash<<<dim3(Tt / 128, Bb * NH), 256>>>();

    k_proj<<<dim3(DM / 128, (Bb * Tt) / 128), 256, GSMEM4>>>(out);
}